// round 8
// baseline (speedup 1.0000x reference)
#include <cuda_runtime.h>
#include <cuda_fp16.h>
#include <cuda_bf16.h>
#include <cstdint>

// Problem constants
#define IN_F    4096
#define OUT_F   11008
#define M_ROWS  4096
#define NGROUPS 32

// Scratch (no cudaMalloc allowed) — both stored in MMA FRAGMENT layout.
// A: [m16_tile (256)][k16_tile (256)][lane (32)][8 halves]  = 32MB
// B: [n8_tile (1376)][k32_chunk (128)][lane (32)][8 halves] = 90MB
__device__ __align__(16) __half g_Af[(size_t)M_ROWS * IN_F];
__device__ __align__(16) __half g_Bf[(size_t)OUT_F * IN_F];
__device__ float  g_scales[NGROUPS * OUT_F];
__device__ int    g_bad_f16;
__device__ int    g_bad_bf16;

// ---------------------------------------------------------------------------
// scales dtype probe (unchanged from passing rounds)
// ---------------------------------------------------------------------------
__global__ void probe_init() { g_bad_f16 = 0; g_bad_bf16 = 0; }

__global__ void probe_kernel(const void* __restrict__ scales) {
    int i = blockIdx.x * blockDim.x + threadIdx.x;
    if (i >= 176128) return;
    float vf = __half2float(((const __half*)scales)[i]);
    if (!(vf >= 0.0f && vf < 1.0f)) atomicExch(&g_bad_f16, 1);
    float vb = __bfloat162float(((const __nv_bfloat16*)scales)[i]);
    if (!(vb >= 0.0f && vb < 1.0f)) atomicExch(&g_bad_bf16, 1);
}

__global__ void cvt_scales(const void* __restrict__ scales) {
    int i = blockIdx.x * blockDim.x + threadIdx.x;
    if (i >= NGROUPS * OUT_F) return;
    float v;
    if (!g_bad_f16)       v = __half2float(((const __half*)scales)[i]);
    else if (!g_bad_bf16) v = __bfloat162float(((const __nv_bfloat16*)scales)[i]);
    else                  v = ((const float*)scales)[i];
    g_scales[i] = v;
}

// ---------------------------------------------------------------------------
// x (fp32) -> A fragments.
// mma m16n8k16 A-frag (row-major A), lane l, tile (m16,k16):
//  a0 = A[m16*16 + l/4      ][k16*16 + 2(l%4) .. +1]
//  a1 = A[m16*16 + l/4 + 8  ][same k]
//  a2 = A[m16*16 + l/4      ][k16*16 + 2(l%4)+8 .. +9]
//  a3 = A[m16*16 + l/4 + 8  ][same k]
// ---------------------------------------------------------------------------
__global__ __launch_bounds__(256) void cvtA_kernel(const float* __restrict__ x) {
    const int w    = threadIdx.x >> 5;
    const int lane = threadIdx.x & 31;
    const int tile = blockIdx.x * 8 + w;       // 65536 tiles
    const int m16  = tile >> 8;
    const int k16  = tile & 255;
    const int row  = m16 * 16 + (lane >> 2);
    const int col  = k16 * 16 + 2 * (lane & 3);

    const float2* X = reinterpret_cast<const float2*>(x);
    float2 f0 = X[((size_t)row       * IN_F + col)     >> 1];
    float2 f1 = X[((size_t)(row + 8) * IN_F + col)     >> 1];
    float2 f2 = X[((size_t)row       * IN_F + col + 8) >> 1];
    float2 f3 = X[((size_t)(row + 8) * IN_F + col + 8) >> 1];

    __half2 h0 = __floats2half2_rn(f0.x, f0.y);
    __half2 h1 = __floats2half2_rn(f1.x, f1.y);
    __half2 h2 = __floats2half2_rn(f2.x, f2.y);
    __half2 h3 = __floats2half2_rn(f3.x, f3.y);

    uint4 o;
    o.x = *reinterpret_cast<uint32_t*>(&h0);
    o.y = *reinterpret_cast<uint32_t*>(&h1);
    o.z = *reinterpret_cast<uint32_t*>(&h2);
    o.w = *reinterpret_cast<uint32_t*>(&h3);
    reinterpret_cast<uint4*>(g_Af)[(size_t)tile * 32 + lane] = o;
}

// ---------------------------------------------------------------------------
// Dequant -> B fragments.
// mma m16n8k16 B-frag (col-major B), lane l, tile (n8, k16):
//  b0 = W[n8*8 + l/4][k16*16 + 2(l%4) .. +1]
//  b1 = W[n8*8 + l/4][k16*16 + 2(l%4)+8 .. +9]
// Packed per k32 chunk c: 16B = {b0(ks0), b1(ks0), b0(ks1), b1(ks1)}.
// Warp handles one (n8, c); lane l: n = n8*8 + l/4, p = l%4;
// qrow i of chunk covers k-local 8i..8i+7; pair (2p,2p+1) of qrow i =
// nibbles at bits (8p..8p+7) of q_i. Same dequant arithmetic as validated.
// ---------------------------------------------------------------------------
__global__ __launch_bounds__(256) void dequant_kernel(
    const int* __restrict__ qweight, const int* __restrict__ qzeros)
{
    const int w    = threadIdx.x >> 5;
    const int lane = threadIdx.x & 31;
    const int idx  = blockIdx.x * 8 + w;       // (n8, c):  1376*128 total
    const int n8   = idx >> 7;
    const int c    = idx & 127;
    const int n    = n8 * 8 + (lane >> 2);
    const int p    = lane & 3;
    const int g    = c >> 2;                   // group = (c*32)/128

    const int z = (qzeros[g * (OUT_F / 8) + (n >> 3)] >> ((n & 7) * 4)) & 15;
    const __half2 s2  = __half2half2(__float2half(g_scales[g * OUT_F + n]));
    const __half2 mz2 = __half2half2(__float2half((float)(1024 + z)));

    uint32_t o[4];
    #pragma unroll
    for (int i = 0; i < 4; i++) {
        const uint32_t q = (uint32_t)qweight[(size_t)(c * 4 + i) * OUT_F + n];
        const uint32_t v = q >> (8 * p);
        uint32_t t = (v & 0xFu) | ((v << 12) & 0x000F0000u) | 0x64006400u;
        __half2 r = __hmul2(__hsub2(*(__half2*)&t, mz2), s2);
        o[i] = *(uint32_t*)&r;
    }
    uint4 ov = make_uint4(o[0], o[1], o[2], o[3]);
    reinterpret_cast<uint4*>(g_Bf)[((size_t)n8 * 128 + c) * 32 + lane] = ov;
}

// ---------------------------------------------------------------------------
// HGEMM, no shared memory: operands streamed L1->registers in fragment
// layout. CTA 128x128, 4 warps (2m x 2n), warp 64x64, k-step 32.
// Per warp-iter: 16 x LDG.128 + 64 x mma.sync. No barriers anywhere.
// ---------------------------------------------------------------------------
constexpr int NIT = IN_F / 32;            // 128 k32 chunks

__global__ __launch_bounds__(128, 2) void gemm_kernel(
    const float* __restrict__ bias, float* __restrict__ out)
{
    const int tid  = threadIdx.x;
    const int lane = tid & 31;
    const int warp = tid >> 5;
    const int warp_m = warp & 1;
    const int warp_n = warp >> 1;

    // grid: m fastest -> A (32MB, L2-resident) reused across n-bands
    const int pid_m = blockIdx.x & 31;       // 32
    const int pid_n = blockIdx.x >> 5;       // 86
    const int m_base = pid_m * 128;
    const int n_base = pid_n * 128;

    // fragment base pointers (uint4 granularity)
    const int m16b = pid_m * 8 + warp_m * 4;     // first of 4 m16 tiles
    const int n8b  = pid_n * 16 + warp_n * 8;    // first of 8 n8 tiles
    const uint4* pA = reinterpret_cast<const uint4*>(g_Af)
                      + (size_t)m16b * 256 * 32 + lane;
    const uint4* pB = reinterpret_cast<const uint4*>(g_Bf)
                      + (size_t)n8b * 128 * 32 + lane;

    float acc[4][8][4];
    #pragma unroll
    for (int mi = 0; mi < 4; mi++)
        #pragma unroll
        for (int ni = 0; ni < 8; ni++)
            #pragma unroll
            for (int r = 0; r < 4; r++) acc[mi][ni][r] = 0.f;

    for (int c = 0; c < NIT; c++) {
        uint4 av[4][2];                      // [mi][ks]
        uint4 bv[8];                         // [nt], 16B = both ks
        #pragma unroll
        for (int mi = 0; mi < 4; mi++) {
            av[mi][0] = pA[mi * (256 * 32) + (2 * c)     * 32];
            av[mi][1] = pA[mi * (256 * 32) + (2 * c + 1) * 32];
        }
        #pragma unroll
        for (int nt = 0; nt < 8; nt++)
            bv[nt] = pB[nt * (128 * 32) + c * 32];

        #pragma unroll
        for (int ks = 0; ks < 2; ks++) {
            #pragma unroll
            for (int mi = 0; mi < 4; mi++) {
                #pragma unroll
                for (int nt = 0; nt < 8; nt++) {
                    uint32_t b0 = ks ? bv[nt].z : bv[nt].x;
                    uint32_t b1 = ks ? bv[nt].w : bv[nt].y;
                    asm volatile(
                        "mma.sync.aligned.m16n8k16.row.col.f32.f16.f16.f32 "
                        "{%0,%1,%2,%3}, {%4,%5,%6,%7}, {%8,%9}, {%0,%1,%2,%3};"
                        : "+f"(acc[mi][nt][0]), "+f"(acc[mi][nt][1]),
                          "+f"(acc[mi][nt][2]), "+f"(acc[mi][nt][3])
                        : "r"(av[mi][ks].x), "r"(av[mi][ks].y),
                          "r"(av[mi][ks].z), "r"(av[mi][ks].w),
                          "r"(b0), "r"(b1));
                }
            }
        }
    }

    // epilogue (same frag->gmem mapping as validated rounds)
    #pragma unroll
    for (int mi = 0; mi < 4; mi++) {
        int row0 = m_base + warp_m * 64 + mi * 16 + (lane >> 2);
        #pragma unroll
        for (int ni = 0; ni < 8; ni++) {
            int col = n_base + warp_n * 64 + ni * 8 + ((lane & 3) << 1);
            float b0 = bias[col], b1 = bias[col + 1];
            float2 v0 = make_float2(acc[mi][ni][0] + b0, acc[mi][ni][1] + b1);
            float2 v1 = make_float2(acc[mi][ni][2] + b0, acc[mi][ni][3] + b1);
            *reinterpret_cast<float2*>(out + (size_t)row0 * OUT_F + col)       = v0;
            *reinterpret_cast<float2*>(out + (size_t)(row0 + 8) * OUT_F + col) = v1;
        }
    }
}

// ---------------------------------------------------------------------------
extern "C" void kernel_launch(void* const* d_in, const int* in_sizes, int n_in,
                              void* d_out, int out_size)
{
    const void *p_x = nullptr, *p_qw = nullptr, *p_qz = nullptr,
               *p_sc = nullptr, *p_b = nullptr;
    for (int i = 0; i < n_in; i++) {
        switch (in_sizes[i]) {
            case M_ROWS * IN_F:        p_x  = d_in[i]; break;
            case (IN_F / 8) * OUT_F:   p_qw = d_in[i]; break;
            case NGROUPS * (OUT_F/8):  p_qz = d_in[i]; break;
            case NGROUPS * OUT_F:      p_sc = d_in[i]; break;
            case OUT_F:                p_b  = d_in[i]; break;
        }
    }

    probe_init<<<1, 1>>>();
    probe_kernel<<<(176128 + 255) / 256, 256>>>(p_sc);
    cvt_scales<<<(NGROUPS * OUT_F + 255) / 256, 256>>>(p_sc);

    // A fragments: 65536 (m16,k16) tiles, 8 per 256-thread block
    cvtA_kernel<<<65536 / 8, 256>>>((const float*)p_x);
    // B fragments: 1376*128 (n8,k32) pairs, 8 per block
    dequant_kernel<<<(1376 * 128) / 8, 256>>>((const int*)p_qw,
                                              (const int*)p_qz);

    // grid: 32 m-tiles x 86 n-tiles, m fastest; no dynamic smem
    gemm_kernel<<<32 * 86, 128>>>((const float*)p_b, (float*)d_out);
}